// round 6
// baseline (speedup 1.0000x reference)
#include <cuda_runtime.h>
#include <cstdint>
#include <cstddef>
#include <math.h>

#define SEQ    2048
#define BATCH  64
#define HID    512
#define NCTA   128
#define NTHR   512

typedef unsigned long long u64;

// ---------------- device globals (allocation-free scratch) ----------------
__device__ unsigned g_flags[NCTA];   // monotonic per-CTA arrival counters
__device__ float g_h0_all[(size_t)SEQ * BATCH * HID];
__device__ float g_h1_all[(size_t)SEQ * BATCH * HID];

// ---------------- packed fp32x2 + memory-model helpers ----------------
__device__ __forceinline__ u64 ffma2(u64 a, u64 b, u64 c) {
    u64 d;
    asm("fma.rn.f32x2 %0, %1, %2, %3;" : "=l"(d) : "l"(a), "l"(b), "l"(c));
    return d;
}
__device__ __forceinline__ u64 fadd2(u64 a, u64 b) {
    u64 d;
    asm("add.rn.f32x2 %0, %1, %2;" : "=l"(d) : "l"(a), "l"(b));
    return d;
}
__device__ __forceinline__ u64 splat2(float x) {
    u64 d;
    asm("mov.b64 %0, {%1, %1};" : "=l"(d) : "f"(x));
    return d;
}
__device__ __forceinline__ float f2lo(u64 v) { return __uint_as_float((unsigned)v); }
__device__ __forceinline__ float f2hi(u64 v) { return __uint_as_float((unsigned)(v >> 32)); }

__device__ __forceinline__ u64 shflx64(u64 v, int m) {
    unsigned lo = (unsigned)v, hi = (unsigned)(v >> 32);
    lo = __shfl_xor_sync(0xffffffffu, lo, m);
    hi = __shfl_xor_sync(0xffffffffu, hi, m);
    return ((u64)hi << 32) | (u64)lo;
}
__device__ __forceinline__ u64 shfli64(u64 v, int src) {
    unsigned lo = (unsigned)v, hi = (unsigned)(v >> 32);
    lo = __shfl_sync(0xffffffffu, lo, src);
    hi = __shfl_sync(0xffffffffu, hi, src);
    return ((u64)hi << 32) | (u64)lo;
}
__device__ __forceinline__ unsigned ld_rlx(const unsigned* p) {
    unsigned v;
    asm volatile("ld.relaxed.gpu.u32 %0, [%1];" : "=r"(v) : "l"(p));
    return v;
}
__device__ __forceinline__ void st_rlx(unsigned* p, unsigned v) {
    asm volatile("st.relaxed.gpu.u32 [%0], %1;" :: "l"(p), "r"(v) : "memory");
}
__device__ __forceinline__ void fence_acq() {
    asm volatile("fence.acq_rel.gpu;" ::: "memory");
}
__device__ __forceinline__ float sigf(float x) { return 1.0f / (1.0f + __expf(-x)); }
__device__ __forceinline__ float tanhfast(float x) {
    return 2.0f / (1.0f + __expf(-2.0f * x)) - 1.0f;
}

// =====================================================================
// Persistent fused LSTM layer, v4.
//  - Quad-XOR swizzle (quad^ (k&7)) on weights + activations:
//    all compute loads are LDS.128, conflict-free; weights need NO MOVs
//    (ulonglong2 loads give natural f32x2 register pairs).
//  - Staging: coalesced 4xLDG.32 batch-gather -> 1 STS.128 per quad.
//  - Atomic-free flag barrier: parallel release stores, 128-thread poll.
//  - Cross-step pipeline: x-projection of t+1 runs after arrive(t).
// =====================================================================
template<int DIN>
__global__ void __launch_bounds__(NTHR, 1)
lstm_layer(const float* __restrict__ x,       // [SEQ][BATCH][DIN]
           const float* __restrict__ h0l,     // [BATCH][HID]
           const float* __restrict__ c0l,     // [BATCH][HID]
           const float* __restrict__ w_ih,    // [4H][DIN]
           const float* __restrict__ w_hh,    // [4H][HID]
           const float* __restrict__ b_ih,    // [4H]
           const float* __restrict__ b_hh,    // [4H]
           float* __restrict__ h_all)         // [SEQ][BATCH][HID]
{
    constexpr int K   = HID + DIN;            // 768 or 1024
    constexpr int NXC = DIN / 256;            // 1 or 2 x-chunks

    extern __shared__ float smem[];
    float* w_sm    = smem;                    // K*32  (quad-swizzled, rg-major)
    float* buf0    = w_sm + K * 32;           // 256*32 (quad-swizzled batches)
    float* buf1    = buf0 + 256 * 32;         // 256*32
    float* bias_sm = buf1 + 256 * 32;         // 32 (pair-major)

    const int tid  = threadIdx.x;
    const int lane = tid & 31;
    const int wrp  = tid >> 5;                // 0..15
    const int rg   = wrp & 3;                 // hu-pair group
    const int bg   = wrp >> 2;                // batch group (8 batches)
    const int hu_base = (blockIdx.x >> 1) * 8;
    const int bbase   = (blockIdx.x & 1) * 32;

    // ---- one-time: weights into SMEM, rg-major pairs, quad-XOR swizzle ----
    // pair p' = rg*4 + gate holds (W[row,k], W[row+1,k]) for hu pair 2rg.
    // quad Q = p'>>1 stored at Q ^ (k&7).
    for (int r = 0; r < 32; r++) {
        int gate = r >> 3, hl = r & 7;
        int rgf = hl >> 1;
        int R = gate * HID + hu_base + hl;
        int qnat = 2 * rgf + (gate >> 1);
        int sub  = ((gate & 1) << 1) | (hl & 1);
        const float* wr_h = w_hh + (size_t)R * HID;
        const float* wr_x = w_ih + (size_t)R * DIN;
        for (int k = tid; k < K; k += NTHR) {
            float v = (k < HID) ? wr_h[k] : wr_x[k - HID];
            w_sm[k * 32 + ((qnat ^ (k & 7)) << 2) + sub] = v;
        }
    }
    if (tid < 32) {
        int gate = tid >> 3, hl = tid & 7;
        int R = gate * HID + hu_base + hl;
        int pair = (hl >> 1) * 4 + gate;
        bias_sm[pair * 2 + (hl & 1)] = b_ih[R] + b_hh[R];
    }

    __shared__ unsigned s_base;
    if (tid == 0) s_base = ld_rlx(&g_flags[blockIdx.x]);
    __syncthreads();                          // covers weights/bias too
    const unsigned base = s_base;

    u64 bias2[4];
#pragma unroll
    for (int g = 0; g < 4; g++) bias2[g] = ((const u64*)bias_sm)[rg * 4 + g];

    // constant swizzled quad offsets (k&7 == lane&7 along the k-split)
    const int q0off = ((2 * rg)     ^ (lane & 7)) << 2;
    const int q1off = ((2 * rg + 1) ^ (lane & 7)) << 2;
    const int a0off = ((2 * bg)     ^ (lane & 7)) << 2;
    const int a1off = ((2 * bg + 1) ^ (lane & 7)) << 2;

    const int bb  = bg * 8 + (lane & 7);
    const int hu0 = hu_base + rg * 2;
    float c0r = c0l[(size_t)(bbase + bb) * HID + hu0];
    float c1r = c0l[(size_t)(bbase + bb) * HID + hu0 + 1];

    u64 acc[4][8];
#pragma unroll
    for (int g = 0; g < 4; g++)
#pragma unroll
        for (int b = 0; b < 8; b++) acc[g][b] = 0ull;

    // staging identity: thread stages batch-quad C at k = 32*(kg0+2i)+lane
    const int stC   = wrp & 7;
    const int stKg0 = wrp >> 3;
    const int stCo  = (stC ^ (lane & 7)) << 2;     // swizzled quad offset

    auto stage = [&](float* buf, const float* src, int stride, int koff) {
        const float* s0 = src + (size_t)(bbase + 4 * stC) * stride + koff;
#pragma unroll
        for (int i = 0; i < 4; i++) {
            int k = 32 * (stKg0 + 2 * i) + lane;
            const float* s = s0 + k;
            float v0 = __ldg(s);
            float v1 = __ldg(s + stride);
            float v2 = __ldg(s + 2 * stride);
            float v3 = __ldg(s + 3 * stride);
            *(float4*)(buf + k * 32 + stCo) = make_float4(v0, v1, v2, v3);
        }
    };

    auto compute = [&](const float* buf, int kbase) {
        const float* wp = w_sm + (size_t)(kbase + lane) * 32;
        const float* ap = buf + lane * 32;
#pragma unroll
        for (int j = 0; j < 8; j++) {
            u64 w2[4];
            {
                ulonglong2 wA = *(const ulonglong2*)(wp + j * 1024 + q0off);
                ulonglong2 wB = *(const ulonglong2*)(wp + j * 1024 + q1off);
                w2[0] = wA.x; w2[1] = wA.y; w2[2] = wB.x; w2[3] = wB.y;
            }
            float4 aA = *(const float4*)(ap + j * 1024 + a0off);
            float4 aB = *(const float4*)(ap + j * 1024 + a1off);
            u64 a2[8];
            a2[0] = splat2(aA.x); a2[1] = splat2(aA.y);
            a2[2] = splat2(aA.z); a2[3] = splat2(aA.w);
            a2[4] = splat2(aB.x); a2[5] = splat2(aB.y);
            a2[6] = splat2(aB.z); a2[7] = splat2(aB.w);
#pragma unroll
            for (int b = 0; b < 8; b++)
#pragma unroll
                for (int g = 0; g < 4; g++)
                    acc[g][b] = ffma2(w2[g], a2[b], acc[g][b]);
        }
    };

#define ACCF(i) acc[(i) >> 3][(i) & 7]

    // ---- prologue: x-projection of step 0 ----
    stage(buf0, x, DIN, 0);
    __syncthreads();
    if constexpr (NXC == 2) {
        stage(buf1, x, DIN, 256);
        compute(buf0, HID);
        __syncthreads();
        compute(buf1, HID + 256);
    } else {
        compute(buf0, HID);
    }

    for (int t = 0; t < SEQ; ++t) {
        const float* __restrict__ hprev =
            t ? (h_all + (size_t)(t - 1) * BATCH * HID) : h0l;

        // ---- flag barrier wait: all CTAs arrived for step t-1 ----
        if (t > 0) {
            if (tid < NCTA) {
                unsigned target = base + (unsigned)t;
                while ((int)(ld_rlx(&g_flags[tid]) - target) < 0) __nanosleep(32);
                fence_acq();
            }
        }
        __syncthreads();

        // ---- h-part: 2 chunks, pipelined ----
        stage(buf0, hprev, HID, 0);
        __syncthreads();
        stage(buf1, hprev, HID, 256);
        compute(buf0, 0);
        __syncthreads();
        if (t + 1 < SEQ)
            stage(buf0, x + (size_t)(t + 1) * BATCH * DIN, DIN, 0);
        compute(buf1, 256);

        // ---- selection-compaction reduction over 32 k-lanes ----
#pragma unroll
        for (int i = 0; i < 16; i++) {
            u64 lo = ACCF(i), hi = ACCF(i + 16);
            u64 mine = (lane & 16) ? hi : lo;
            u64 give = (lane & 16) ? lo : hi;
            ACCF(i) = fadd2(mine, shflx64(give, 16));
        }
#pragma unroll
        for (int i = 0; i < 8; i++) {
            u64 lo = ACCF(i), hi = ACCF(i + 8);
            u64 mine = (lane & 8) ? hi : lo;
            u64 give = (lane & 8) ? lo : hi;
            ACCF(i) = fadd2(mine, shflx64(give, 8));
        }
#pragma unroll
        for (int i = 0; i < 4; i++) {
            u64 lo = ACCF(i), hi = ACCF(i + 4);
            u64 mine = (lane & 4) ? hi : lo;
            u64 give = (lane & 4) ? lo : hi;
            ACCF(i) = fadd2(mine, shflx64(give, 4));
        }
#pragma unroll
        for (int i = 0; i < 2; i++) {
            u64 lo = ACCF(i), hi = ACCF(i + 2);
            u64 mine = (lane & 2) ? hi : lo;
            u64 give = (lane & 2) ? lo : hi;
            ACCF(i) = fadd2(mine, shflx64(give, 2));
        }
        {
            u64 lo = ACCF(0), hi = ACCF(1);
            u64 mine = (lane & 1) ? hi : lo;
            u64 give = (lane & 1) ? lo : hi;
            ACCF(0) = fadd2(mine, shflx64(give, 1));
        }
        u64 fin = ACCF(0);

        u64 gv[4];
#pragma unroll
        for (int g = 0; g < 4; g++)
            gv[g] = fadd2(shfli64(fin, g * 8 + (lane & 7)), bias2[g]);

        float ig0 = sigf(f2lo(gv[0])), ig1 = sigf(f2hi(gv[0]));
        float fg0 = sigf(f2lo(gv[1])), fg1 = sigf(f2hi(gv[1]));
        float gg0 = tanhfast(f2lo(gv[2])), gg1 = tanhfast(f2hi(gv[2]));
        float og0 = sigf(f2lo(gv[3])), og1 = sigf(f2hi(gv[3]));
        c0r = fg0 * c0r + ig0 * gg0;
        c1r = fg1 * c1r + ig1 * gg1;
        float h0v = og0 * tanhfast(c0r);
        float h1v = og1 * tanhfast(c1r);

        if (lane < 8)
            *(float2*)&h_all[((size_t)t * BATCH + bbase + bb) * HID + hu0] =
                make_float2(h0v, h1v);

        // zero acc for next step's x accumulation
#pragma unroll
        for (int g = 0; g < 4; g++)
#pragma unroll
            for (int b = 0; b < 8; b++) acc[g][b] = 0ull;

        if (t + 1 < SEQ) {
            __threadfence();
            __syncthreads();                 // h stores fenced; Xc0 STS done
            if (tid == 0) st_rlx(&g_flags[blockIdx.x], base + (unsigned)(t + 1));
            // x-projection of step t+1 overlaps other CTAs' progress + barrier
            if constexpr (NXC == 2) {
                stage(buf1, x + (size_t)(t + 1) * BATCH * DIN, DIN, 256);
                compute(buf0, HID);
                __syncthreads();
                compute(buf1, HID + 256);
            } else {
                compute(buf0, HID);
            }
        }
    }
#undef ACCF
}

// ---------------- output head: sigmoid(h1 . w_out + b_out) ----------------
__global__ void __launch_bounds__(256)
head_kernel(const float* __restrict__ h_all, const float* __restrict__ w_out,
            const float* __restrict__ b_out, float* __restrict__ out)
{
    __shared__ float wsm[HID];
    int t = blockIdx.x;
    for (int i = threadIdx.x; i < HID; i += 256) wsm[i] = w_out[i];
    __syncthreads();
    int wrp = threadIdx.x >> 5, lane = threadIdx.x & 31;
    float bo = b_out[0];
#pragma unroll
    for (int rb = 0; rb < 8; ++rb) {
        int b = wrp * 8 + rb;
        const float* h = h_all + ((size_t)t * BATCH + b) * HID;
        float s = 0.f;
#pragma unroll
        for (int j = 0; j < 16; ++j) s += h[lane + 32 * j] * wsm[lane + 32 * j];
#pragma unroll
        for (int m = 16; m > 0; m >>= 1) s += __shfl_xor_sync(0xffffffffu, s, m);
        if (lane == 0) out[(size_t)t * BATCH + b] = 1.f / (1.f + expf(-(s + bo)));
    }
}

extern "C" void kernel_launch(void* const* d_in, const int* in_sizes, int n_in,
                              void* d_out, int out_size)
{
    (void)in_sizes; (void)n_in; (void)out_size;
    const float* input = (const float*)d_in[0];
    const float* h0    = (const float*)d_in[1];
    const float* c0    = (const float*)d_in[2];
    const float* w_ih0 = (const float*)d_in[3];
    const float* w_hh0 = (const float*)d_in[4];
    const float* b_ih0 = (const float*)d_in[5];
    const float* b_hh0 = (const float*)d_in[6];
    const float* w_ih1 = (const float*)d_in[7];
    const float* w_hh1 = (const float*)d_in[8];
    const float* b_ih1 = (const float*)d_in[9];
    const float* b_hh1 = (const float*)d_in[10];
    const float* w_out = (const float*)d_in[11];
    const float* b_out = (const float*)d_in[12];
    float* out = (float*)d_out;

    float* h0p = nullptr;
    float* h1p = nullptr;
    cudaGetSymbolAddress((void**)&h0p, g_h0_all);
    cudaGetSymbolAddress((void**)&h1p, g_h1_all);

    const int smem0 = (768  * 32 + 2 * 256 * 32 + 32) * (int)sizeof(float); // 163,968
    const int smem1 = (1024 * 32 + 2 * 256 * 32 + 32) * (int)sizeof(float); // 196,736
    cudaFuncSetAttribute(lstm_layer<256>, cudaFuncAttributeMaxDynamicSharedMemorySize, smem0);
    cudaFuncSetAttribute(lstm_layer<512>, cudaFuncAttributeMaxDynamicSharedMemorySize, smem1);

    lstm_layer<256><<<NCTA, NTHR, smem0>>>(input, h0, c0,
                                           w_ih0, w_hh0, b_ih0, b_hh0, h0p);
    lstm_layer<512><<<NCTA, NTHR, smem1>>>(h0p, h0 + BATCH * HID, c0 + BATCH * HID,
                                           w_ih1, w_hh1, b_ih1, b_hh1, h1p);
    head_kernel<<<SEQ, 256>>>(h1p, w_out, b_out, out);
}

// round 7
// speedup vs baseline: 1.0086x; 1.0086x over previous
#include <cuda_runtime.h>
#include <cstdint>
#include <cstddef>
#include <math.h>

#define SEQ    2048
#define BATCH  64
#define HID    512
#define NCTA   128
#define NTHR   512

typedef unsigned long long u64;

// ---------------- device globals (allocation-free scratch) ----------------
__device__ __align__(8) unsigned g_flags[NCTA];  // [half*64 + hu_tile], monotonic
__device__ float g_h0_all[(size_t)SEQ * BATCH * HID];
__device__ float g_h1_all[(size_t)SEQ * BATCH * HID];

// ---------------- packed fp32x2 + memory-model helpers ----------------
__device__ __forceinline__ u64 ffma2(u64 a, u64 b, u64 c) {
    u64 d;
    asm("fma.rn.f32x2 %0, %1, %2, %3;" : "=l"(d) : "l"(a), "l"(b), "l"(c));
    return d;
}
__device__ __forceinline__ u64 fadd2(u64 a, u64 b) {
    u64 d;
    asm("add.rn.f32x2 %0, %1, %2;" : "=l"(d) : "l"(a), "l"(b));
    return d;
}
__device__ __forceinline__ u64 splat2(float x) {
    u64 d;
    asm("mov.b64 %0, {%1, %1};" : "=l"(d) : "f"(x));
    return d;
}
__device__ __forceinline__ float f2lo(u64 v) { return __uint_as_float((unsigned)v); }
__device__ __forceinline__ float f2hi(u64 v) { return __uint_as_float((unsigned)(v >> 32)); }

__device__ __forceinline__ u64 shflx64(u64 v, int m) {
    unsigned lo = (unsigned)v, hi = (unsigned)(v >> 32);
    lo = __shfl_xor_sync(0xffffffffu, lo, m);
    hi = __shfl_xor_sync(0xffffffffu, hi, m);
    return ((u64)hi << 32) | (u64)lo;
}
__device__ __forceinline__ u64 shfli64(u64 v, int src) {
    unsigned lo = (unsigned)v, hi = (unsigned)(v >> 32);
    lo = __shfl_sync(0xffffffffu, lo, src);
    hi = __shfl_sync(0xffffffffu, hi, src);
    return ((u64)hi << 32) | (u64)lo;
}
__device__ __forceinline__ unsigned ld_rlx(const unsigned* p) {
    unsigned v;
    asm volatile("ld.relaxed.gpu.u32 %0, [%1];" : "=r"(v) : "l"(p));
    return v;
}
__device__ __forceinline__ void ld_rlx2(const unsigned* p, unsigned& a, unsigned& b) {
    asm volatile("ld.relaxed.gpu.v2.u32 {%0,%1}, [%2];"
                 : "=r"(a), "=r"(b) : "l"(p));
}
__device__ __forceinline__ void st_rlx(unsigned* p, unsigned v) {
    asm volatile("st.relaxed.gpu.u32 [%0], %1;" :: "l"(p), "r"(v) : "memory");
}
__device__ __forceinline__ void fence_acq() {
    asm volatile("fence.acq_rel.gpu;" ::: "memory");
}
__device__ __forceinline__ float sigf(float x) { return 1.0f / (1.0f + __expf(-x)); }
__device__ __forceinline__ float tanhfast(float x) {
    return 2.0f / (1.0f + __expf(-2.0f * x)) - 1.0f;
}

// =====================================================================
// Persistent fused LSTM layer, v5: latency surgery.
//  - Tight spin flag poll (warp 0, v2 loads, no nanosleep).
//  - Independent barrier per batch half (64 contiguous flags each).
//  - 3 act buffers: both h chunks staged together (one sync), computed
//    back-to-back; x(t+1) staged+computed after arrive (covers barrier).
//  - Quad-XOR swizzle -> all compute loads LDS.128, conflict-free;
//    FFMA2 micro-tile 4 gate-pairs x 8 batches.
// =====================================================================
template<int DIN>
__global__ void __launch_bounds__(NTHR, 1)
lstm_layer(const float* __restrict__ x,       // [SEQ][BATCH][DIN]
           const float* __restrict__ h0l,     // [BATCH][HID]
           const float* __restrict__ c0l,     // [BATCH][HID]
           const float* __restrict__ w_ih,    // [4H][DIN]
           const float* __restrict__ w_hh,    // [4H][HID]
           const float* __restrict__ b_ih,    // [4H]
           const float* __restrict__ b_hh,    // [4H]
           float* __restrict__ h_all)         // [SEQ][BATCH][HID]
{
    constexpr int K   = HID + DIN;            // 768 or 1024
    constexpr int NXC = DIN / 256;            // 1 or 2 x-chunks

    extern __shared__ float smem[];
    float* w_sm    = smem;                    // K*32  (quad-swizzled, rg-major)
    float* buf0    = w_sm + K * 32;           // 256*32
    float* buf1    = buf0 + 256 * 32;         // 256*32
    float* buf2    = buf1 + 256 * 32;         // 256*32
    float* bias_sm = buf2 + 256 * 32;         // 32 (pair-major)

    const int tid  = threadIdx.x;
    const int lane = tid & 31;
    const int wrp  = tid >> 5;                // 0..15
    const int rg   = wrp & 3;                 // hu-pair group
    const int bg   = wrp >> 2;                // batch group (8 batches)
    const int half = blockIdx.x & 1;          // batch half
    const int hu_base = (blockIdx.x >> 1) * 8;
    const int bbase   = half * 32;
    const int fidx    = half * 64 + (blockIdx.x >> 1);

    // ---- one-time: weights into SMEM, rg-major pairs, quad-XOR swizzle ----
    for (int r = 0; r < 32; r++) {
        int gate = r >> 3, hl = r & 7;
        int rgf = hl >> 1;
        int R = gate * HID + hu_base + hl;
        int qnat = 2 * rgf + (gate >> 1);
        int sub  = ((gate & 1) << 1) | (hl & 1);
        const float* wr_h = w_hh + (size_t)R * HID;
        const float* wr_x = w_ih + (size_t)R * DIN;
        for (int k = tid; k < K; k += NTHR) {
            float v = (k < HID) ? wr_h[k] : wr_x[k - HID];
            w_sm[k * 32 + ((qnat ^ (k & 7)) << 2) + sub] = v;
        }
    }
    if (tid < 32) {
        int gate = tid >> 3, hl = tid & 7;
        int R = gate * HID + hu_base + hl;
        int pair = (hl >> 1) * 4 + gate;
        bias_sm[pair * 2 + (hl & 1)] = b_ih[R] + b_hh[R];
    }

    __shared__ unsigned s_base;
    if (tid == 0) s_base = ld_rlx(&g_flags[fidx]);
    __syncthreads();                          // covers weights/bias too
    const unsigned base = s_base;

    u64 bias2[4];
#pragma unroll
    for (int g = 0; g < 4; g++) bias2[g] = ((const u64*)bias_sm)[rg * 4 + g];

    const int q0off = ((2 * rg)     ^ (lane & 7)) << 2;
    const int q1off = ((2 * rg + 1) ^ (lane & 7)) << 2;
    const int a0off = ((2 * bg)     ^ (lane & 7)) << 2;
    const int a1off = ((2 * bg + 1) ^ (lane & 7)) << 2;

    const int bb  = bg * 8 + (lane & 7);
    const int hu0 = hu_base + rg * 2;
    float c0r = c0l[(size_t)(bbase + bb) * HID + hu0];
    float c1r = c0l[(size_t)(bbase + bb) * HID + hu0 + 1];

    u64 acc[4][8];
#pragma unroll
    for (int g = 0; g < 4; g++)
#pragma unroll
        for (int b = 0; b < 8; b++) acc[g][b] = 0ull;

    // staging identity: thread stages batch-quad stC at k = 32*(stKg0+2i)+lane
    const int stC   = wrp & 7;
    const int stKg0 = wrp >> 3;
    const int stCo  = (stC ^ (lane & 7)) << 2;

    auto stage = [&](float* buf, const float* src, int stride, int koff) {
        const float* s0 = src + (size_t)(bbase + 4 * stC) * stride + koff;
#pragma unroll
        for (int i = 0; i < 4; i++) {
            int k = 32 * (stKg0 + 2 * i) + lane;
            const float* s = s0 + k;
            float v0 = __ldg(s);
            float v1 = __ldg(s + stride);
            float v2 = __ldg(s + 2 * stride);
            float v3 = __ldg(s + 3 * stride);
            *(float4*)(buf + k * 32 + stCo) = make_float4(v0, v1, v2, v3);
        }
    };

    auto compute = [&](const float* buf, int kbase) {
        const float* wp = w_sm + (size_t)(kbase + lane) * 32;
        const float* ap = buf + lane * 32;
#pragma unroll
        for (int j = 0; j < 8; j++) {
            u64 w2[4];
            {
                ulonglong2 wA = *(const ulonglong2*)(wp + j * 1024 + q0off);
                ulonglong2 wB = *(const ulonglong2*)(wp + j * 1024 + q1off);
                w2[0] = wA.x; w2[1] = wA.y; w2[2] = wB.x; w2[3] = wB.y;
            }
            float4 aA = *(const float4*)(ap + j * 1024 + a0off);
            float4 aB = *(const float4*)(ap + j * 1024 + a1off);
            u64 a2[8];
            a2[0] = splat2(aA.x); a2[1] = splat2(aA.y);
            a2[2] = splat2(aA.z); a2[3] = splat2(aA.w);
            a2[4] = splat2(aB.x); a2[5] = splat2(aB.y);
            a2[6] = splat2(aB.z); a2[7] = splat2(aB.w);
#pragma unroll
            for (int b = 0; b < 8; b++)
#pragma unroll
                for (int g = 0; g < 4; g++)
                    acc[g][b] = ffma2(w2[g], a2[b], acc[g][b]);
        }
    };

#define ACCF(i) acc[(i) >> 3][(i) & 7]

    // ---- prologue: x-projection of step 0 ----
    stage(buf2, x, DIN, 0);
    if constexpr (NXC == 2) stage(buf0, x, DIN, 256);
    __syncthreads();
    compute(buf2, HID);
    if constexpr (NXC == 2) compute(buf0, HID + 256);

    for (int t = 0; t < SEQ; ++t) {
        const float* __restrict__ hprev =
            t ? (h_all + (size_t)(t - 1) * BATCH * HID) : h0l;

        // ---- tight spin poll on own half's 64 flags (warp 0 only) ----
        if (t > 0 && wrp == 0) {
            const unsigned target = base + (unsigned)t;
            const unsigned* fp = g_flags + half * 64 + lane * 2;
            for (;;) {
                unsigned a, b;
                ld_rlx2(fp, a, b);
                if ((int)(a - target) >= 0 && (int)(b - target) >= 0) break;
            }
            fence_acq();
        }
        __syncthreads();   // join poll; also orders prior x-compute vs restage

        // ---- h-part: stage both chunks, then compute both ----
        stage(buf0, hprev, HID, 0);
        stage(buf1, hprev, HID, 256);
        __syncthreads();
        compute(buf0, 0);
        compute(buf1, 256);

        // ---- selection-compaction reduction over 32 k-lanes ----
#pragma unroll
        for (int i = 0; i < 16; i++) {
            u64 lo = ACCF(i), hi = ACCF(i + 16);
            u64 mine = (lane & 16) ? hi : lo;
            u64 give = (lane & 16) ? lo : hi;
            ACCF(i) = fadd2(mine, shflx64(give, 16));
        }
#pragma unroll
        for (int i = 0; i < 8; i++) {
            u64 lo = ACCF(i), hi = ACCF(i + 8);
            u64 mine = (lane & 8) ? hi : lo;
            u64 give = (lane & 8) ? lo : hi;
            ACCF(i) = fadd2(mine, shflx64(give, 8));
        }
#pragma unroll
        for (int i = 0; i < 4; i++) {
            u64 lo = ACCF(i), hi = ACCF(i + 4);
            u64 mine = (lane & 4) ? hi : lo;
            u64 give = (lane & 4) ? lo : hi;
            ACCF(i) = fadd2(mine, shflx64(give, 4));
        }
#pragma unroll
        for (int i = 0; i < 2; i++) {
            u64 lo = ACCF(i), hi = ACCF(i + 2);
            u64 mine = (lane & 2) ? hi : lo;
            u64 give = (lane & 2) ? lo : hi;
            ACCF(i) = fadd2(mine, shflx64(give, 2));
        }
        {
            u64 lo = ACCF(0), hi = ACCF(1);
            u64 mine = (lane & 1) ? hi : lo;
            u64 give = (lane & 1) ? lo : hi;
            ACCF(0) = fadd2(mine, shflx64(give, 1));
        }
        u64 fin = ACCF(0);

        u64 gv[4];
#pragma unroll
        for (int g = 0; g < 4; g++)
            gv[g] = fadd2(shfli64(fin, g * 8 + (lane & 7)), bias2[g]);

        float ig0 = sigf(f2lo(gv[0])), ig1 = sigf(f2hi(gv[0]));
        float fg0 = sigf(f2lo(gv[1])), fg1 = sigf(f2hi(gv[1]));
        float gg0 = tanhfast(f2lo(gv[2])), gg1 = tanhfast(f2hi(gv[2]));
        float og0 = sigf(f2lo(gv[3])), og1 = sigf(f2hi(gv[3]));
        c0r = fg0 * c0r + ig0 * gg0;
        c1r = fg1 * c1r + ig1 * gg1;
        float h0v = og0 * tanhfast(c0r);
        float h1v = og1 * tanhfast(c1r);

        if (lane < 8)
            *(float2*)&h_all[((size_t)t * BATCH + bbase + bb) * HID + hu0] =
                make_float2(h0v, h1v);

        // zero acc for next step's x accumulation
#pragma unroll
        for (int g = 0; g < 4; g++)
#pragma unroll
            for (int b = 0; b < 8; b++) acc[g][b] = 0ull;

        if (t + 1 < SEQ) {
            __threadfence();
            __syncthreads();                  // all h stores fenced
            if (tid == 0) st_rlx(&g_flags[fidx], base + (unsigned)(t + 1));
            // x-projection of step t+1: covers barrier propagation
            const float* xn = x + (size_t)(t + 1) * BATCH * DIN;
            stage(buf2, xn, DIN, 0);
            if constexpr (NXC == 2) stage(buf0, xn, DIN, 256);
            __syncthreads();
            compute(buf2, HID);
            if constexpr (NXC == 2) compute(buf0, HID + 256);
        }
    }
#undef ACCF
}

// ---------------- output head: sigmoid(h1 . w_out + b_out) ----------------
__global__ void __launch_bounds__(256)
head_kernel(const float* __restrict__ h_all, const float* __restrict__ w_out,
            const float* __restrict__ b_out, float* __restrict__ out)
{
    __shared__ float wsm[HID];
    int t = blockIdx.x;
    for (int i = threadIdx.x; i < HID; i += 256) wsm[i] = w_out[i];
    __syncthreads();
    int wrp = threadIdx.x >> 5, lane = threadIdx.x & 31;
    float bo = b_out[0];
#pragma unroll
    for (int rb = 0; rb < 8; ++rb) {
        int b = wrp * 8 + rb;
        const float* h = h_all + ((size_t)t * BATCH + b) * HID;
        float s = 0.f;
#pragma unroll
        for (int j = 0; j < 16; ++j) s += h[lane + 32 * j] * wsm[lane + 32 * j];
#pragma unroll
        for (int m = 16; m > 0; m >>= 1) s += __shfl_xor_sync(0xffffffffu, s, m);
        if (lane == 0) out[(size_t)t * BATCH + b] = 1.f / (1.f + expf(-(s + bo)));
    }
}

extern "C" void kernel_launch(void* const* d_in, const int* in_sizes, int n_in,
                              void* d_out, int out_size)
{
    (void)in_sizes; (void)n_in; (void)out_size;
    const float* input = (const float*)d_in[0];
    const float* h0    = (const float*)d_in[1];
    const float* c0    = (const float*)d_in[2];
    const float* w_ih0 = (const float*)d_in[3];
    const float* w_hh0 = (const float*)d_in[4];
    const float* b_ih0 = (const float*)d_in[5];
    const float* b_hh0 = (const float*)d_in[6];
    const float* w_ih1 = (const float*)d_in[7];
    const float* w_hh1 = (const float*)d_in[8];
    const float* b_ih1 = (const float*)d_in[9];
    const float* b_hh1 = (const float*)d_in[10];
    const float* w_out = (const float*)d_in[11];
    const float* b_out = (const float*)d_in[12];
    float* out = (float*)d_out;

    float* h0p = nullptr;
    float* h1p = nullptr;
    cudaGetSymbolAddress((void**)&h0p, g_h0_all);
    cudaGetSymbolAddress((void**)&h1p, g_h1_all);

    const int smem0 = (768  * 32 + 3 * 256 * 32 + 32) * (int)sizeof(float); // 196,736
    const int smem1 = (1024 * 32 + 3 * 256 * 32 + 32) * (int)sizeof(float); // 229,504
    cudaFuncSetAttribute(lstm_layer<256>, cudaFuncAttributeMaxDynamicSharedMemorySize, smem0);
    cudaFuncSetAttribute(lstm_layer<512>, cudaFuncAttributeMaxDynamicSharedMemorySize, smem1);

    lstm_layer<256><<<NCTA, NTHR, smem0>>>(input, h0, c0,
                                           w_ih0, w_hh0, b_ih0, b_hh0, h0p);
    lstm_layer<512><<<NCTA, NTHR, smem1>>>(h0p, h0 + BATCH * HID, c0 + BATCH * HID,
                                           w_ih1, w_hh1, b_ih1, b_hh1, h1p);
    head_kernel<<<SEQ, 256>>>(h1p, w_out, b_out, out);
}